// round 14
// baseline (speedup 1.0000x reference)
#include <cuda_runtime.h>
#include <cuda_fp16.h>
#include <cstdint>

#define NN 100000
#define NE 1600000
#define IND 128
#define HD 64
#define SCAN_BLOCKS 391   // ceil(NN/256)

// -------- scratch (no allocation allowed: __device__ globals) --------
__device__ int   g_deg_out[NN];
__device__ int   g_deg_in[NN];
__device__ int   g_start[NN];          // CSR row start, block-local exclusive
__device__ int   g_bsum[SCAN_BLOCKS];  // after scan1: exclusive block offsets
__device__ int   g_scan_done;
__device__ __align__(16) int g_rel[NE];           // per-edge bucket ticket
__device__ __align__(16) int g_esrc[NE];          // edge sources grouped by dst
__device__ __align__(16) __half2 g_x1h[NN * 32];  // layer-1 feats (fp16)
__device__ __align__(16) float   g_agg1[NN * HD]; // layer-1 aggregation (fp32)
__device__ __align__(16) __half2 g_x2h[NN * 32];  // layer-2 feats (fp16)

// -------- init: zero degree counters --------
__global__ void k_init() {
    int i = blockIdx.x * blockDim.x + threadIdx.x;
    if (i < NN) {
        g_deg_out[i] = 0;
        g_deg_in[i] = 0;
    }
    if (i == 0) g_scan_done = 0;
}

// -------- degree histograms; the deg_in ticket IS the placement slot --------
__global__ void k_deg(const int* __restrict__ src, const int* __restrict__ dst) {
    int i = blockIdx.x * blockDim.x + threadIdx.x;
    if (i < NE) {
        g_rel[i] = atomicAdd(&g_deg_in[dst[i]], 1);
        atomicAdd(&g_deg_out[src[i]], 1);
    }
}

// -------- scan1: block-local exclusive scan of deg_in; last block scans bsums --------
__global__ void k_scan1() {
    __shared__ int wt[8];
    __shared__ bool is_last;
    int tid = threadIdx.x;
    int lane = tid & 31;
    int wid = tid >> 5;
    int i = blockIdx.x * 256 + tid;

    int v = (i < NN) ? g_deg_in[i] : 0;
    int x = v;
#pragma unroll
    for (int off = 1; off < 32; off <<= 1) {
        int t = __shfl_up_sync(0xffffffffu, x, off);
        if (lane >= off) x += t;
    }
    if (lane == 31) wt[wid] = x;
    __syncthreads();
    if (wid == 0 && lane < 8) {
        int w = wt[lane];
#pragma unroll
        for (int off = 1; off < 8; off <<= 1) {
            int t = __shfl_up_sync(0x000000ffu, w, off);
            if (lane >= off) w += t;
        }
        wt[lane] = w;
    }
    __syncthreads();
    int base = (wid > 0) ? wt[wid - 1] : 0;
    int incl = base + x;
    if (i < NN) g_start[i] = incl - v;            // block-local exclusive
    if (tid == 255) g_bsum[blockIdx.x] = incl;    // block total

    // ---- last block scans the block sums (fused) ----
    __threadfence();
    if (tid == 0) {
        int d = atomicAdd(&g_scan_done, 1);
        is_last = (d == (int)gridDim.x - 1);
    }
    __syncthreads();
    if (!is_last) return;
    __threadfence();

    int v0 = (2 * tid < SCAN_BLOCKS) ? g_bsum[2 * tid] : 0;
    int v1 = (2 * tid + 1 < SCAN_BLOCKS) ? g_bsum[2 * tid + 1] : 0;
    int p = v0 + v1;
    int y = p;
#pragma unroll
    for (int off = 1; off < 32; off <<= 1) {
        int t = __shfl_up_sync(0xffffffffu, y, off);
        if (lane >= off) y += t;
    }
    __syncthreads();   // wt reuse barrier
    if (lane == 31) wt[wid] = y;
    __syncthreads();
    if (wid == 0 && lane < 8) {
        int w = wt[lane];
#pragma unroll
        for (int off = 1; off < 8; off <<= 1) {
            int t = __shfl_up_sync(0x000000ffu, w, off);
            if (lane >= off) w += t;
        }
        wt[lane] = w;
    }
    __syncthreads();
    int base2 = (wid > 0) ? wt[wid - 1] : 0;
    int ex = base2 + y - p;
    if (2 * tid < SCAN_BLOCKS) g_bsum[2 * tid] = ex;
    if (2 * tid + 1 < SCAN_BLOCKS) g_bsum[2 * tid + 1] = ex + v0;
}

// -------- CSR placement: NO atomics — pos = start + bsum + saved ticket --------
__global__ void k_place(const int* __restrict__ src, const int* __restrict__ dst) {
    int i = blockIdx.x * blockDim.x + threadIdx.x;
    if (i < NE) {
        int d = dst[i];
        int pos = g_start[d] + g_bsum[d >> 8] + g_rel[i];
        g_esrc[pos] = src[i];
    }
}

// ============================================================================
// TF32 tensor-core GEMM helpers (mma.sync m16n8k8)
// ============================================================================
__device__ __forceinline__ uint32_t f2tf32(float f) {
    uint32_t r;
    asm("cvt.rna.tf32.f32 %0, %1;" : "=r"(r) : "f"(f));
    return r;
}

__device__ __forceinline__ void mma_tf32(float c[4],
                                         uint32_t a0, uint32_t a1,
                                         uint32_t a2, uint32_t a3,
                                         uint32_t b0, uint32_t b1) {
    asm volatile(
        "mma.sync.aligned.m16n8k8.row.col.f32.tf32.tf32.f32 "
        "{%0,%1,%2,%3}, {%4,%5,%6,%7}, {%8,%9}, {%0,%1,%2,%3};"
        : "+f"(c[0]), "+f"(c[1]), "+f"(c[2]), "+f"(c[3])
        : "r"(a0), "r"(a1), "r"(a2), "r"(a3), "r"(b0), "r"(b1));
}

__device__ __forceinline__ float deg2norm(int deg) {
    return rsqrtf(fmaxf((float)deg, 1.f));
}

#define ASTR 36
#define BSTR 72
#define KCHUNK 32

// ============================================================================
// GEMM1: x1 = ((h @ W1) * norm_src)  -> fp16 store; norm inline from deg_out
// ============================================================================
__global__ __launch_bounds__(256) void k_gemm1(const float* __restrict__ h,
                                               const float* __restrict__ W1) {
    __shared__ uint32_t As[128 * ASTR];
    __shared__ uint32_t Bs[KCHUNK * BSTR];
    int tid = threadIdx.x;
    int w = tid >> 5;
    int lane = tid & 31;
    int q = lane >> 2;
    int cc = lane & 3;
    int row0 = blockIdx.x * 128;

    float c[8][4];
#pragma unroll
    for (int nt = 0; nt < 8; nt++)
#pragma unroll
        for (int j = 0; j < 4; j++) c[nt][j] = 0.f;

#pragma unroll 1
    for (int kc = 0; kc < IND / KCHUNK; kc++) {
        int k0 = kc * KCHUNK;
        __syncthreads();
        for (int i = tid; i < KCHUNK * HD; i += 256) {
            int kk = i >> 6, n = i & 63;
            Bs[kk * BSTR + n] = f2tf32(W1[(k0 + kk) * HD + n]);
        }
        for (int i = tid; i < 128 * KCHUNK; i += 256) {
            int r = i >> 5, kk = i & 31;
            int row = row0 + r;
            float v = (row < NN) ? h[row * IND + k0 + kk] : 0.f;
            As[r * ASTR + kk] = f2tf32(v);
        }
        __syncthreads();

        const uint32_t* ap = As + (w * 16 + q) * ASTR + cc;
#pragma unroll
        for (int ks = 0; ks < 4; ks++) {
            uint32_t a0 = ap[ks * 8];
            uint32_t a1 = ap[8 * ASTR + ks * 8];
            uint32_t a2 = ap[ks * 8 + 4];
            uint32_t a3 = ap[8 * ASTR + ks * 8 + 4];
            const uint32_t* bp = Bs + (ks * 8 + cc) * BSTR + q;
#pragma unroll
            for (int nt = 0; nt < 8; nt++) {
                uint32_t b0 = bp[nt * 8];
                uint32_t b1 = bp[4 * BSTR + nt * 8];
                mma_tf32(c[nt], a0, a1, a2, a3, b0, b1);
            }
        }
    }

    int r0g = row0 + w * 16 + q;
    int r1g = r0g + 8;
    float ns0 = (r0g < NN) ? deg2norm(g_deg_out[r0g]) : 0.f;
    float ns1 = (r1g < NN) ? deg2norm(g_deg_out[r1g]) : 0.f;
#pragma unroll
    for (int nt = 0; nt < 8; nt++) {
        int h2col = nt * 4 + cc;
        if (r0g < NN)
            g_x1h[r0g * 32 + h2col] = __floats2half2_rn(c[nt][0] * ns0, c[nt][1] * ns0);
        if (r1g < NN)
            g_x1h[r1g * 32 + h2col] = __floats2half2_rn(c[nt][2] * ns1, c[nt][3] * ns1);
    }
}

// ============================================================================
// GEMM2: x2 = (elu(agg1*norm_dst + b1) * norm_src) @ W2 -> fp16 store
// ============================================================================
__global__ __launch_bounds__(256) void k_gemm2(const float* __restrict__ b1,
                                               const float* __restrict__ W2) {
    __shared__ uint32_t As[128 * ASTR];
    __shared__ uint32_t Bs[KCHUNK * BSTR];
    __shared__ float b1s[HD];
    __shared__ float nds[128], nss[128];
    int tid = threadIdx.x;
    int w = tid >> 5;
    int lane = tid & 31;
    int q = lane >> 2;
    int cc = lane & 3;
    int row0 = blockIdx.x * 128;

    if (tid < HD) b1s[tid] = b1[tid];
    if (tid < 128) {
        int row = row0 + tid;
        nds[tid] = (row < NN) ? deg2norm(g_deg_in[row]) : 0.f;
        nss[tid] = (row < NN) ? deg2norm(g_deg_out[row]) : 0.f;
    }

    float c[8][4];
#pragma unroll
    for (int nt = 0; nt < 8; nt++)
#pragma unroll
        for (int j = 0; j < 4; j++) c[nt][j] = 0.f;

#pragma unroll 1
    for (int kc = 0; kc < HD / KCHUNK; kc++) {
        int k0 = kc * KCHUNK;
        __syncthreads();
        for (int i = tid; i < KCHUNK * HD; i += 256) {
            int kk = i >> 6, n = i & 63;
            Bs[kk * BSTR + n] = f2tf32(W2[(k0 + kk) * HD + n]);
        }
        for (int i = tid; i < 128 * KCHUNK; i += 256) {
            int r = i >> 5, kk = i & 31;
            int row = row0 + r;
            float v = 0.f;
            if (row < NN) {
                int k = k0 + kk;
                v = g_agg1[row * HD + k] * nds[r] + b1s[k];
                v = (v > 0.f) ? v : expm1f(v);
                v *= nss[r];
            }
            As[r * ASTR + kk] = f2tf32(v);
        }
        __syncthreads();

        const uint32_t* ap = As + (w * 16 + q) * ASTR + cc;
#pragma unroll
        for (int ks = 0; ks < 4; ks++) {
            uint32_t a0 = ap[ks * 8];
            uint32_t a1 = ap[8 * ASTR + ks * 8];
            uint32_t a2 = ap[ks * 8 + 4];
            uint32_t a3 = ap[8 * ASTR + ks * 8 + 4];
            const uint32_t* bp = Bs + (ks * 8 + cc) * BSTR + q;
#pragma unroll
            for (int nt = 0; nt < 8; nt++) {
                uint32_t b0 = bp[nt * 8];
                uint32_t b1r = bp[4 * BSTR + nt * 8];
                mma_tf32(c[nt], a0, a1, a2, a3, b0, b1r);
            }
        }
    }

    int r0g = row0 + w * 16 + q;
    int r1g = r0g + 8;
#pragma unroll
    for (int nt = 0; nt < 8; nt++) {
        int h2col = nt * 4 + cc;
        if (r0g < NN)
            g_x2h[r0g * 32 + h2col] = __floats2half2_rn(c[nt][0], c[nt][1]);
        if (r1g < NN)
            g_x2h[r1g * 32 + h2col] = __floats2half2_rn(c[nt][2], c[nt][3]);
    }
}

// ============================================================================
// CSR aggregation: warp per node; 16 lanes cover one 128B row via uint2,
// each gather LDG.64 fetches TWO edges' rows. fp32 accumulation, no atomics.
// ============================================================================
__device__ __forceinline__ float4 agg_row_u2(const uint2* __restrict__ xh,
                                             int n, int lane) {
    int sub = lane >> 4;   // which edge of the pair
    int c = lane & 15;     // uint2 column (4 half cols)
    int start = g_start[n] + g_bsum[n >> 8];
    int end = start + g_deg_in[n];
    float4 acc = make_float4(0.f, 0.f, 0.f, 0.f);
    int e = start;

    for (; e + 8 <= end; e += 8) {
#pragma unroll
        for (int kp = 0; kp < 4; kp++) {
            int s = __ldg(&g_esrc[e + 2 * kp + sub]);
            uint2 u = __ldg(&xh[s * 16 + c]);
            float2 f0 = __half22float2(*reinterpret_cast<__half2*>(&u.x));
            float2 f1 = __half22float2(*reinterpret_cast<__half2*>(&u.y));
            acc.x += f0.x; acc.y += f0.y;
            acc.z += f1.x; acc.w += f1.y;
        }
    }
    for (; e < end; e += 2) {
        int e2 = e + sub;
        if (e2 < end) {
            int s = __ldg(&g_esrc[e2]);
            uint2 u = __ldg(&xh[s * 16 + c]);
            float2 f0 = __half22float2(*reinterpret_cast<__half2*>(&u.x));
            float2 f1 = __half22float2(*reinterpret_cast<__half2*>(&u.y));
            acc.x += f0.x; acc.y += f0.y;
            acc.z += f1.x; acc.w += f1.y;
        }
    }
    acc.x += __shfl_down_sync(0xffffffffu, acc.x, 16);
    acc.y += __shfl_down_sync(0xffffffffu, acc.y, 16);
    acc.z += __shfl_down_sync(0xffffffffu, acc.z, 16);
    acc.w += __shfl_down_sync(0xffffffffu, acc.w, 16);
    return acc;
}

__global__ __launch_bounds__(256) void k_agg1() {
    int n = (blockIdx.x * 256 + threadIdx.x) >> 5;
    int lane = threadIdx.x & 31;
    if (n >= NN) return;
    float4 acc = agg_row_u2(reinterpret_cast<const uint2*>(g_x1h), n, lane);
    if (lane < 16)
        reinterpret_cast<float4*>(g_agg1)[n * 16 + lane] = acc;
}

// layer-2 aggregation with fused finalize: out = agg*norm_dst + b2
__global__ __launch_bounds__(256) void k_agg2(float* __restrict__ out,
                                              const float* __restrict__ b2) {
    int n = (blockIdx.x * 256 + threadIdx.x) >> 5;
    int lane = threadIdx.x & 31;
    if (n >= NN) return;
    float4 acc = agg_row_u2(reinterpret_cast<const uint2*>(g_x2h), n, lane);
    if (lane < 16) {
        float nd = deg2norm(g_deg_in[n]);
        float4 bb = __ldg(reinterpret_cast<const float4*>(b2) + lane);
        float4 o = make_float4(acc.x * nd + bb.x, acc.y * nd + bb.y,
                               acc.z * nd + bb.z, acc.w * nd + bb.w);
        reinterpret_cast<float4*>(out)[n * 16 + lane] = o;
    }
}

extern "C" void kernel_launch(void* const* d_in, const int* in_sizes, int n_in,
                              void* d_out, int out_size) {
    const float* h   = (const float*)d_in[0];
    const int*   src = (const int*)d_in[1];
    const int*   dst = (const int*)d_in[2];
    const float* W1  = (const float*)d_in[3];
    const float* b1  = (const float*)d_in[4];
    const float* W2  = (const float*)d_in[5];
    const float* b2  = (const float*)d_in[6];
    float* out = (float*)d_out;

    const int GBLK = (NN + 127) / 128;           // 782
    const int AGG_BLK = (NN * 32 + 255) / 256;   // warp per node

    // ---- graph preprocessing (CSR by dst), 4 launches ----
    k_init<<<(NN + 255) / 256, 256>>>();
    k_deg<<<(NE + 255) / 256, 256>>>(src, dst);  // saves per-edge ticket
    k_scan1<<<SCAN_BLOCKS, 256>>>();             // + fused block-sum scan
    k_place<<<(NE + 255) / 256, 256>>>(src, dst);// atomic-free

    // ---- layer 1 ----
    k_gemm1<<<GBLK, 256>>>(h, W1);
    k_agg1<<<AGG_BLK, 256>>>();

    // ---- layer 2 ----
    k_gemm2<<<GBLK, 256>>>(b1, W2);
    k_agg2<<<AGG_BLK, 256>>>(out, b2);
}

// round 15
// speedup vs baseline: 1.2982x; 1.2982x over previous
#include <cuda_runtime.h>
#include <cuda_fp16.h>
#include <cstdint>

#define NN 100000
#define NE 1600000
#define IND 128
#define HD 64
#define SCAN_BLOCKS 391   // ceil(NN/256)

// -------- scratch (no allocation allowed: __device__ globals) --------
__device__ int   g_deg_out[NN];
__device__ int   g_deg_in[NN];
__device__ int   g_start[NN];          // CSR row start, block-local exclusive
__device__ int   g_cur0[NN];           // relative placement cursors (zeroed)
__device__ int   g_bsum[SCAN_BLOCKS];  // after scan1: exclusive block offsets
__device__ int   g_scan_done;
__device__ __align__(16) int g_esrc[NE];          // edge sources grouped by dst
__device__ __align__(16) __half2 g_x1h[NN * 32];  // layer-1 feats (fp16)
__device__ __align__(16) float   g_agg1[NN * HD]; // layer-1 aggregation (fp32)
__device__ __align__(16) __half2 g_x2h[NN * 32];  // layer-2 feats (fp16)

// -------- init: zero counters --------
__global__ void k_init() {
    int i = blockIdx.x * blockDim.x + threadIdx.x;
    if (i < NN) {
        g_deg_out[i] = 0;
        g_deg_in[i] = 0;
        g_cur0[i] = 0;
    }
    if (i == 0) g_scan_done = 0;
}

// -------- degree histograms: 4 edges/thread, int4 loads, returnless REDs --------
__global__ void k_deg(const int4* __restrict__ src4, const int4* __restrict__ dst4) {
    int i = blockIdx.x * blockDim.x + threadIdx.x;
    if (i < NE / 4) {
        int4 s = __ldg(&src4[i]);
        int4 d = __ldg(&dst4[i]);
        atomicAdd(&g_deg_out[s.x], 1);
        atomicAdd(&g_deg_out[s.y], 1);
        atomicAdd(&g_deg_out[s.z], 1);
        atomicAdd(&g_deg_out[s.w], 1);
        atomicAdd(&g_deg_in[d.x], 1);
        atomicAdd(&g_deg_in[d.y], 1);
        atomicAdd(&g_deg_in[d.z], 1);
        atomicAdd(&g_deg_in[d.w], 1);
    }
}

// -------- scan1: block-local exclusive scan of deg_in; last block scans bsums --------
__global__ void k_scan1() {
    __shared__ int wt[8];
    __shared__ bool is_last;
    int tid = threadIdx.x;
    int lane = tid & 31;
    int wid = tid >> 5;
    int i = blockIdx.x * 256 + tid;

    int v = (i < NN) ? g_deg_in[i] : 0;
    int x = v;
#pragma unroll
    for (int off = 1; off < 32; off <<= 1) {
        int t = __shfl_up_sync(0xffffffffu, x, off);
        if (lane >= off) x += t;
    }
    if (lane == 31) wt[wid] = x;
    __syncthreads();
    if (wid == 0 && lane < 8) {
        int w = wt[lane];
#pragma unroll
        for (int off = 1; off < 8; off <<= 1) {
            int t = __shfl_up_sync(0x000000ffu, w, off);
            if (lane >= off) w += t;
        }
        wt[lane] = w;
    }
    __syncthreads();
    int base = (wid > 0) ? wt[wid - 1] : 0;
    int incl = base + x;
    if (i < NN) g_start[i] = incl - v;            // block-local exclusive
    if (tid == 255) g_bsum[blockIdx.x] = incl;    // block total

    // ---- last block scans the block sums (fused) ----
    __threadfence();
    if (tid == 0) {
        int d = atomicAdd(&g_scan_done, 1);
        is_last = (d == (int)gridDim.x - 1);
    }
    __syncthreads();
    if (!is_last) return;
    __threadfence();

    int v0 = (2 * tid < SCAN_BLOCKS) ? g_bsum[2 * tid] : 0;
    int v1 = (2 * tid + 1 < SCAN_BLOCKS) ? g_bsum[2 * tid + 1] : 0;
    int p = v0 + v1;
    int y = p;
#pragma unroll
    for (int off = 1; off < 32; off <<= 1) {
        int t = __shfl_up_sync(0xffffffffu, y, off);
        if (lane >= off) y += t;
    }
    __syncthreads();   // wt reuse barrier
    if (lane == 31) wt[wid] = y;
    __syncthreads();
    if (wid == 0 && lane < 8) {
        int w = wt[lane];
#pragma unroll
        for (int off = 1; off < 8; off <<= 1) {
            int t = __shfl_up_sync(0x000000ffu, w, off);
            if (lane >= off) w += t;
        }
        wt[lane] = w;
    }
    __syncthreads();
    int base2 = (wid > 0) ? wt[wid - 1] : 0;
    int ex = base2 + y - p;
    if (2 * tid < SCAN_BLOCKS) g_bsum[2 * tid] = ex;
    if (2 * tid + 1 < SCAN_BLOCKS) g_bsum[2 * tid + 1] = ex + v0;
}

// -------- CSR placement: 4 edges/thread for MLP on the atomic+store chain --------
__global__ void k_place(const int4* __restrict__ src4, const int4* __restrict__ dst4) {
    int i = blockIdx.x * blockDim.x + threadIdx.x;
    if (i < NE / 4) {
        int4 s = __ldg(&src4[i]);
        int4 d = __ldg(&dst4[i]);
        int r0 = atomicAdd(&g_cur0[d.x], 1);
        int r1 = atomicAdd(&g_cur0[d.y], 1);
        int r2 = atomicAdd(&g_cur0[d.z], 1);
        int r3 = atomicAdd(&g_cur0[d.w], 1);
        g_esrc[g_start[d.x] + g_bsum[d.x >> 8] + r0] = s.x;
        g_esrc[g_start[d.y] + g_bsum[d.y >> 8] + r1] = s.y;
        g_esrc[g_start[d.z] + g_bsum[d.z >> 8] + r2] = s.z;
        g_esrc[g_start[d.w] + g_bsum[d.w >> 8] + r3] = s.w;
    }
}

// ============================================================================
// TF32 tensor-core GEMM helpers (mma.sync m16n8k8)
// ============================================================================
__device__ __forceinline__ uint32_t f2tf32(float f) {
    uint32_t r;
    asm("cvt.rna.tf32.f32 %0, %1;" : "=r"(r) : "f"(f));
    return r;
}

__device__ __forceinline__ void mma_tf32(float c[4],
                                         uint32_t a0, uint32_t a1,
                                         uint32_t a2, uint32_t a3,
                                         uint32_t b0, uint32_t b1) {
    asm volatile(
        "mma.sync.aligned.m16n8k8.row.col.f32.tf32.tf32.f32 "
        "{%0,%1,%2,%3}, {%4,%5,%6,%7}, {%8,%9}, {%0,%1,%2,%3};"
        : "+f"(c[0]), "+f"(c[1]), "+f"(c[2]), "+f"(c[3])
        : "r"(a0), "r"(a1), "r"(a2), "r"(a3), "r"(b0), "r"(b1));
}

__device__ __forceinline__ float deg2norm(int deg) {
    return rsqrtf(fmaxf((float)deg, 1.f));
}

#define ASTR 36
#define BSTR 72
#define KCHUNK 32

// ============================================================================
// GEMM1: x1 = ((h @ W1) * norm_src)  -> fp16 store; norm inline from deg_out
// ============================================================================
__global__ __launch_bounds__(256) void k_gemm1(const float* __restrict__ h,
                                               const float* __restrict__ W1) {
    __shared__ uint32_t As[128 * ASTR];
    __shared__ uint32_t Bs[KCHUNK * BSTR];
    int tid = threadIdx.x;
    int w = tid >> 5;
    int lane = tid & 31;
    int q = lane >> 2;
    int cc = lane & 3;
    int row0 = blockIdx.x * 128;

    float c[8][4];
#pragma unroll
    for (int nt = 0; nt < 8; nt++)
#pragma unroll
        for (int j = 0; j < 4; j++) c[nt][j] = 0.f;

#pragma unroll 1
    for (int kc = 0; kc < IND / KCHUNK; kc++) {
        int k0 = kc * KCHUNK;
        __syncthreads();
        for (int i = tid; i < KCHUNK * HD; i += 256) {
            int kk = i >> 6, n = i & 63;
            Bs[kk * BSTR + n] = f2tf32(W1[(k0 + kk) * HD + n]);
        }
        for (int i = tid; i < 128 * KCHUNK; i += 256) {
            int r = i >> 5, kk = i & 31;
            int row = row0 + r;
            float v = (row < NN) ? h[row * IND + k0 + kk] : 0.f;
            As[r * ASTR + kk] = f2tf32(v);
        }
        __syncthreads();

        const uint32_t* ap = As + (w * 16 + q) * ASTR + cc;
#pragma unroll
        for (int ks = 0; ks < 4; ks++) {
            uint32_t a0 = ap[ks * 8];
            uint32_t a1 = ap[8 * ASTR + ks * 8];
            uint32_t a2 = ap[ks * 8 + 4];
            uint32_t a3 = ap[8 * ASTR + ks * 8 + 4];
            const uint32_t* bp = Bs + (ks * 8 + cc) * BSTR + q;
#pragma unroll
            for (int nt = 0; nt < 8; nt++) {
                uint32_t b0 = bp[nt * 8];
                uint32_t b1 = bp[4 * BSTR + nt * 8];
                mma_tf32(c[nt], a0, a1, a2, a3, b0, b1);
            }
        }
    }

    int r0g = row0 + w * 16 + q;
    int r1g = r0g + 8;
    float ns0 = (r0g < NN) ? deg2norm(g_deg_out[r0g]) : 0.f;
    float ns1 = (r1g < NN) ? deg2norm(g_deg_out[r1g]) : 0.f;
#pragma unroll
    for (int nt = 0; nt < 8; nt++) {
        int h2col = nt * 4 + cc;
        if (r0g < NN)
            g_x1h[r0g * 32 + h2col] = __floats2half2_rn(c[nt][0] * ns0, c[nt][1] * ns0);
        if (r1g < NN)
            g_x1h[r1g * 32 + h2col] = __floats2half2_rn(c[nt][2] * ns1, c[nt][3] * ns1);
    }
}

// ============================================================================
// GEMM2: x2 = (elu(agg1*norm_dst + b1) * norm_src) @ W2 -> fp16 store
// ============================================================================
__global__ __launch_bounds__(256) void k_gemm2(const float* __restrict__ b1,
                                               const float* __restrict__ W2) {
    __shared__ uint32_t As[128 * ASTR];
    __shared__ uint32_t Bs[KCHUNK * BSTR];
    __shared__ float b1s[HD];
    __shared__ float nds[128], nss[128];
    int tid = threadIdx.x;
    int w = tid >> 5;
    int lane = tid & 31;
    int q = lane >> 2;
    int cc = lane & 3;
    int row0 = blockIdx.x * 128;

    if (tid < HD) b1s[tid] = b1[tid];
    if (tid < 128) {
        int row = row0 + tid;
        nds[tid] = (row < NN) ? deg2norm(g_deg_in[row]) : 0.f;
        nss[tid] = (row < NN) ? deg2norm(g_deg_out[row]) : 0.f;
    }

    float c[8][4];
#pragma unroll
    for (int nt = 0; nt < 8; nt++)
#pragma unroll
        for (int j = 0; j < 4; j++) c[nt][j] = 0.f;

#pragma unroll 1
    for (int kc = 0; kc < HD / KCHUNK; kc++) {
        int k0 = kc * KCHUNK;
        __syncthreads();
        for (int i = tid; i < KCHUNK * HD; i += 256) {
            int kk = i >> 6, n = i & 63;
            Bs[kk * BSTR + n] = f2tf32(W2[(k0 + kk) * HD + n]);
        }
        for (int i = tid; i < 128 * KCHUNK; i += 256) {
            int r = i >> 5, kk = i & 31;
            int row = row0 + r;
            float v = 0.f;
            if (row < NN) {
                int k = k0 + kk;
                v = g_agg1[row * HD + k] * nds[r] + b1s[k];
                v = (v > 0.f) ? v : expm1f(v);
                v *= nss[r];
            }
            As[r * ASTR + kk] = f2tf32(v);
        }
        __syncthreads();

        const uint32_t* ap = As + (w * 16 + q) * ASTR + cc;
#pragma unroll
        for (int ks = 0; ks < 4; ks++) {
            uint32_t a0 = ap[ks * 8];
            uint32_t a1 = ap[8 * ASTR + ks * 8];
            uint32_t a2 = ap[ks * 8 + 4];
            uint32_t a3 = ap[8 * ASTR + ks * 8 + 4];
            const uint32_t* bp = Bs + (ks * 8 + cc) * BSTR + q;
#pragma unroll
            for (int nt = 0; nt < 8; nt++) {
                uint32_t b0 = bp[nt * 8];
                uint32_t b1r = bp[4 * BSTR + nt * 8];
                mma_tf32(c[nt], a0, a1, a2, a3, b0, b1r);
            }
        }
    }

    int r0g = row0 + w * 16 + q;
    int r1g = r0g + 8;
#pragma unroll
    for (int nt = 0; nt < 8; nt++) {
        int h2col = nt * 4 + cc;
        if (r0g < NN)
            g_x2h[r0g * 32 + h2col] = __floats2half2_rn(c[nt][0], c[nt][1]);
        if (r1g < NN)
            g_x2h[r1g * 32 + h2col] = __floats2half2_rn(c[nt][2], c[nt][3]);
    }
}

// ============================================================================
// CSR aggregation: warp per node; 16 lanes cover one 128B row via uint2,
// each gather LDG.64 fetches TWO edges' rows. fp32 accumulation, no atomics.
// ============================================================================
__device__ __forceinline__ float4 agg_row_u2(const uint2* __restrict__ xh,
                                             int n, int lane) {
    int sub = lane >> 4;   // which edge of the pair
    int c = lane & 15;     // uint2 column (4 half cols)
    int start = g_start[n] + g_bsum[n >> 8];
    int end = start + g_deg_in[n];
    float4 acc = make_float4(0.f, 0.f, 0.f, 0.f);
    int e = start;

    for (; e + 8 <= end; e += 8) {
#pragma unroll
        for (int kp = 0; kp < 4; kp++) {
            int s = __ldg(&g_esrc[e + 2 * kp + sub]);
            uint2 u = __ldg(&xh[s * 16 + c]);
            float2 f0 = __half22float2(*reinterpret_cast<__half2*>(&u.x));
            float2 f1 = __half22float2(*reinterpret_cast<__half2*>(&u.y));
            acc.x += f0.x; acc.y += f0.y;
            acc.z += f1.x; acc.w += f1.y;
        }
    }
    for (; e < end; e += 2) {
        int e2 = e + sub;
        if (e2 < end) {
            int s = __ldg(&g_esrc[e2]);
            uint2 u = __ldg(&xh[s * 16 + c]);
            float2 f0 = __half22float2(*reinterpret_cast<__half2*>(&u.x));
            float2 f1 = __half22float2(*reinterpret_cast<__half2*>(&u.y));
            acc.x += f0.x; acc.y += f0.y;
            acc.z += f1.x; acc.w += f1.y;
        }
    }
    acc.x += __shfl_down_sync(0xffffffffu, acc.x, 16);
    acc.y += __shfl_down_sync(0xffffffffu, acc.y, 16);
    acc.z += __shfl_down_sync(0xffffffffu, acc.z, 16);
    acc.w += __shfl_down_sync(0xffffffffu, acc.w, 16);
    return acc;
}

__global__ __launch_bounds__(256) void k_agg1() {
    int n = (blockIdx.x * 256 + threadIdx.x) >> 5;
    int lane = threadIdx.x & 31;
    if (n >= NN) return;
    float4 acc = agg_row_u2(reinterpret_cast<const uint2*>(g_x1h), n, lane);
    if (lane < 16)
        reinterpret_cast<float4*>(g_agg1)[n * 16 + lane] = acc;
}

// layer-2 aggregation with fused finalize: out = agg*norm_dst + b2
__global__ __launch_bounds__(256) void k_agg2(float* __restrict__ out,
                                              const float* __restrict__ b2) {
    int n = (blockIdx.x * 256 + threadIdx.x) >> 5;
    int lane = threadIdx.x & 31;
    if (n >= NN) return;
    float4 acc = agg_row_u2(reinterpret_cast<const uint2*>(g_x2h), n, lane);
    if (lane < 16) {
        float nd = deg2norm(g_deg_in[n]);
        float4 bb = __ldg(reinterpret_cast<const float4*>(b2) + lane);
        float4 o = make_float4(acc.x * nd + bb.x, acc.y * nd + bb.y,
                               acc.z * nd + bb.z, acc.w * nd + bb.w);
        reinterpret_cast<float4*>(out)[n * 16 + lane] = o;
    }
}

extern "C" void kernel_launch(void* const* d_in, const int* in_sizes, int n_in,
                              void* d_out, int out_size) {
    const float* h   = (const float*)d_in[0];
    const int*   src = (const int*)d_in[1];
    const int*   dst = (const int*)d_in[2];
    const float* W1  = (const float*)d_in[3];
    const float* b1  = (const float*)d_in[4];
    const float* W2  = (const float*)d_in[5];
    const float* b2  = (const float*)d_in[6];
    float* out = (float*)d_out;

    const int GBLK = (NN + 127) / 128;           // 782
    const int AGG_BLK = (NN * 32 + 255) / 256;   // warp per node
    const int E4_BLK = (NE / 4 + 255) / 256;     // 4 edges per thread

    // ---- graph preprocessing (CSR by dst), 4 launches ----
    k_init<<<(NN + 255) / 256, 256>>>();
    k_deg<<<E4_BLK, 256>>>((const int4*)src, (const int4*)dst);
    k_scan1<<<SCAN_BLOCKS, 256>>>();             // + fused block-sum scan
    k_place<<<E4_BLK, 256>>>((const int4*)src, (const int4*)dst);

    // ---- layer 1 ----
    k_gemm1<<<GBLK, 256>>>(h, W1);
    k_agg1<<<AGG_BLK, 256>>>();

    // ---- layer 2 ----
    k_gemm2<<<GBLK, 256>>>(b1, W2);
    k_agg2<<<AGG_BLK, 256>>>(out, b2);
}